// round 3
// baseline (speedup 1.0000x reference)
#include <cuda_runtime.h>
#include <math.h>

#define NSAMP 4096
#define NFFT 256
#define HOP 64
#define NFRAMES 65
#define NBINS 129
#define NB 64          // batch
#define NE 8           // experts
#define CH 64          // channels
#define L1LEN 2048
#define L2LEN 1024
#define TOUT 64        // output t per tile
#define NTILES (L2LEN / TOUT)

// scratch (no allocations allowed)
__device__ float g_mag[NB * NFRAMES * NBINS];   // per-frame magnitudes
__device__ int   g_eidx[NB * 2];
__device__ float g_ew[NB * 2];

// ---------------------------------------------------------------------------
// Kernel 1: STFT magnitudes. grid (NFRAMES, NB), 256 threads.
// cos(2*pi*k*n/256) depends only on (k*n mod 256) -> 256-entry shared table.
// ---------------------------------------------------------------------------
__global__ void __launch_bounds__(256) k_stft(const float* __restrict__ x) {
    __shared__ float cs[NFFT];
    __shared__ float f[NFFT];
    const int fr = blockIdx.x;
    const int b  = blockIdx.y;
    const int t  = threadIdx.x;

    cs[t] = cospif((float)t / 128.0f);          // cos(2*pi*t/256)
    // reflect-padded sample: xp[j] with j = fr*HOP + t, pad=128
    int m = fr * HOP + t - 128;
    if (m < 0) m = -m;
    else if (m >= NSAMP) m = 2 * NSAMP - 2 - m;
    const float win = 0.5f - 0.5f * cs[t];      // own write, no sync needed yet
    f[t] = x[b * NSAMP + m] * win;
    __syncthreads();

    if (t < NBINS) {
        float re = 0.f, sm = 0.f;
        int idx = 0;
#pragma unroll 8
        for (int n = 0; n < NFFT; n++) {
            const float v = f[n];
            re += v * cs[idx];
            sm += v * cs[(idx + 192) & 255];    // sin(theta) = cos(theta - pi/2)
            idx = (idx + t) & 255;
        }
        g_mag[(b * NFRAMES + fr) * NBINS + t] = sqrtf(re * re + sm * sm);
    }
}

// ---------------------------------------------------------------------------
// Kernel 2: pooling + gating MLP + top-2 + softmax. grid (NB), 256 threads.
// ---------------------------------------------------------------------------
__global__ void __launch_bounds__(256) k_gate(
    const float* __restrict__ Wg1, const float* __restrict__ bg1,
    const float* __restrict__ Wg2, const float* __restrict__ bg2,
    const float* __restrict__ Wg3, const float* __restrict__ bg3) {
    __shared__ float p[NBINS];
    __shared__ float h1[256];
    __shared__ float h2[128];
    __shared__ float lg[NE];
    const int b = blockIdx.x;
    const int t = threadIdx.x;

    if (t < NBINS) {
        float s = 0.f;
        for (int fr = 0; fr < NFRAMES; fr++)
            s += g_mag[(b * NFRAMES + fr) * NBINS + t];
        p[t] = s * (1.0f / NFRAMES);
    }
    __syncthreads();

    {   // 129 -> 256
        float s = bg1[t];
        for (int i = 0; i < NBINS; i++) s += p[i] * Wg1[i * 256 + t];
        h1[t] = fmaxf(s, 0.f);
    }
    __syncthreads();
    if (t < 128) {  // 256 -> 128
        float s = bg2[t];
        for (int i = 0; i < 256; i++) s += h1[i] * Wg2[i * 128 + t];
        h2[t] = fmaxf(s, 0.f);
    }
    __syncthreads();
    if (t < NE) {   // 128 -> 8
        float s = bg3[t];
        for (int i = 0; i < 128; i++) s += h2[i] * Wg3[i * NE + t];
        lg[t] = s;
    }
    __syncthreads();
    if (t == 0) {
        int i0 = 0; float v0 = lg[0];
        for (int j = 1; j < NE; j++) if (lg[j] > v0) { v0 = lg[j]; i0 = j; }
        int i1 = (i0 == 0) ? 1 : 0; float v1 = lg[i1];
        for (int j = 0; j < NE; j++)
            if (j != i0 && lg[j] > v1) { v1 = lg[j]; i1 = j; }
        const float e = expf(v1 - v0);
        const float inv = 1.f / (1.f + e);
        g_eidx[b * 2] = i0; g_eidx[b * 2 + 1] = i1;
        g_ew[b * 2] = inv;  g_ew[b * 2 + 1] = e * inv;
    }
}

// ---------------------------------------------------------------------------
// Kernel 3: fused top-2 expert conv stack.
// grid (NTILES, 3 branches, NB), 256 threads, ~86KB dyn smem (2 blocks/SM).
// conv1 (stride2, pad ksz/2) -> relu -> smem h1 tile; conv2 (k3, stride2,
// pad1) with 4c x 4t register tiles; fused weighted sum of the two experts.
// wbs smem layout: [r=ci*3+k][c ^ ((r&7)<<2)] -> conflict-free float4 reads.
// ---------------------------------------------------------------------------
#define H1STRIDE 132
#define SMEM_FLOATS (272 + 448 + 64 + 64 + 192 * 64 + CH * H1STRIDE)

__global__ void __launch_bounds__(256) k_expert(
    float* __restrict__ out, const float* __restrict__ x,
    const float* __restrict__ wa3, const float* __restrict__ ba3,
    const float* __restrict__ wb3, const float* __restrict__ bb3,
    const float* __restrict__ wa5, const float* __restrict__ ba5,
    const float* __restrict__ wb5, const float* __restrict__ bb5,
    const float* __restrict__ wa7, const float* __restrict__ ba7,
    const float* __restrict__ wb7, const float* __restrict__ bb7) {
    extern __shared__ float smem[];
    float* xs  = smem;          // 272
    float* was = xs + 272;      // up to 64*7
    float* bas = was + 448;     // 64
    float* bbs = bas + 64;      // 64
    float* wbs = bbs + 64;      // 192*64
    float* h1s = wbs + 192 * 64; // 64*132

    const int tid = threadIdx.x;
    const int tile = blockIdx.x;
    const int br   = blockIdx.y;
    const int b    = blockIdx.z;
    const int t0   = tile * TOUT;
    const int ksz  = 3 + 2 * br;
    const int pad  = ksz >> 1;

    const float* wap = (br == 0) ? wa3 : ((br == 1) ? wa5 : wa7);
    const float* bap = (br == 0) ? ba3 : ((br == 1) ? ba5 : ba7);
    const float* wbp = (br == 0) ? wb3 : ((br == 1) ? wb5 : wb7);
    const float* bbp = (br == 0) ? bb3 : ((br == 1) ? bb5 : bb7);

    const int   eidx[2] = { g_eidx[b * 2], g_eidx[b * 2 + 1] };
    const float ewgt[2] = { g_ew[b * 2],   g_ew[b * 2 + 1] };

    // x window for this tile: xi in [4*t0-5, 4*t0+263]
    const int xlo = 4 * t0 - 5;
    for (int i = tid; i < 272; i += 256) {
        const int xi = xlo + i;
        xs[i] = (xi >= 0 && xi < NSAMP) ? x[b * NSAMP + xi] : 0.f;
    }

    const int cg = tid & 15;          // channel group 0..15
    const int tg = tid >> 4;          // t group 0..15
    const int cbase = cg * 4;

    float facc[16];
#pragma unroll
    for (int i = 0; i < 16; i++) facc[i] = 0.f;

    for (int ei = 0; ei < 2; ei++) {
        const int   e   = eidx[ei];
        const float wgt = ewgt[ei];
        __syncthreads();   // xs ready (ei=0) / prev conv2 done reading (ei=1)

        // stage expert weights
        const float* wa = wap + e * CH * ksz;
        for (int i = tid; i < CH * ksz; i += 256) was[i] = wa[i];
        if (tid < CH) {
            bas[tid] = bap[e * CH + tid];
            bbs[tid] = bbp[e * CH + tid];
        }
        const float* wb = wbp + e * CH * CH * 3;
        for (int i = tid; i < CH * 192; i += 256) {   // coalesced gmem read
            const int c = i / 192;
            const int r = i - c * 192;                // ci*3 + k
            wbs[r * 64 + (c ^ ((r & 7) << 2))] = wb[i];
        }
        __syncthreads();

        // conv1 -> h1s[c][j], j=0..128 maps to p = 2*t0 - 1 + j
        for (int idx = tid; idx < CH * H1STRIDE; idx += 256) {
            const int c = idx / H1STRIDE;
            const int j = idx - c * H1STRIDE;
            const int p = 2 * t0 - 1 + j;
            float s = bas[c];
            const float* wr = &was[c * ksz];
            const int off = 2 * j + (3 - pad);
            for (int k = 0; k < ksz; k++) s += wr[k] * xs[off + k];
            h1s[idx] = (p >= 0 && p < L1LEN) ? fmaxf(s, 0.f) : 0.f;
        }
        __syncthreads();

        // conv2: 4 channels x 4 t per thread
        float acc[16];
#pragma unroll
        for (int i = 0; i < 16; i++) acc[i] = 0.f;

#pragma unroll 2
        for (int ci = 0; ci < CH; ci++) {
            const float* hb = &h1s[ci * H1STRIDE + tg * 8];
            const float4 ha = *(const float4*)(hb);
            const float4 hm = *(const float4*)(hb + 4);
            const float4 hc = *(const float4*)(hb + 8);
            const float hh[12] = { ha.x, ha.y, ha.z, ha.w,
                                   hm.x, hm.y, hm.z, hm.w,
                                   hc.x, hc.y, hc.z, hc.w };
            const int r0 = ci * 3;
            const float4 w0 = *(const float4*)&wbs[ r0      * 64 + (cbase ^ (( r0      & 7) << 2))];
            const float4 w1 = *(const float4*)&wbs[(r0 + 1) * 64 + (cbase ^ (((r0 + 1) & 7) << 2))];
            const float4 w2 = *(const float4*)&wbs[(r0 + 2) * 64 + (cbase ^ (((r0 + 2) & 7) << 2))];
            const float wk0[4] = { w0.x, w0.y, w0.z, w0.w };
            const float wk1[4] = { w1.x, w1.y, w1.z, w1.w };
            const float wk2[4] = { w2.x, w2.y, w2.z, w2.w };
#pragma unroll
            for (int i = 0; i < 4; i++)
#pragma unroll
                for (int bt = 0; bt < 4; bt++)
                    acc[i * 4 + bt] += wk0[i] * hh[2 * bt]
                                     + wk1[i] * hh[2 * bt + 1]
                                     + wk2[i] * hh[2 * bt + 2];
        }
#pragma unroll
        for (int i = 0; i < 4; i++) {
            const float bias = bbs[cbase + i];
#pragma unroll
            for (int bt = 0; bt < 4; bt++)
                facc[i * 4 + bt] += wgt * fmaxf(acc[i * 4 + bt] + bias, 0.f);
        }
    }

    const int t_out = t0 + tg * 4;
#pragma unroll
    for (int i = 0; i < 4; i++) {
        const int c_out = br * 64 + cbase + i;
        float4 v = make_float4(facc[i * 4 + 0], facc[i * 4 + 1],
                               facc[i * 4 + 2], facc[i * 4 + 3]);
        *(float4*)&out[((size_t)(b * 192 + c_out)) * L2LEN + t_out] = v;
    }
}

// ---------------------------------------------------------------------------
extern "C" void kernel_launch(void* const* d_in, const int* in_sizes, int n_in,
                              void* d_out, int out_size) {
    const float* x   = (const float*)d_in[0];
    const float* Wg1 = (const float*)d_in[1];
    const float* bg1 = (const float*)d_in[2];
    const float* Wg2 = (const float*)d_in[3];
    const float* bg2 = (const float*)d_in[4];
    const float* Wg3 = (const float*)d_in[5];
    const float* bg3 = (const float*)d_in[6];
    const float* wa3 = (const float*)d_in[7];
    const float* ba3 = (const float*)d_in[8];
    const float* wb3 = (const float*)d_in[9];
    const float* bb3 = (const float*)d_in[10];
    const float* wa5 = (const float*)d_in[11];
    const float* ba5 = (const float*)d_in[12];
    const float* wb5 = (const float*)d_in[13];
    const float* bb5 = (const float*)d_in[14];
    const float* wa7 = (const float*)d_in[15];
    const float* ba7 = (const float*)d_in[16];
    const float* wb7 = (const float*)d_in[17];
    const float* bb7 = (const float*)d_in[18];
    float* out = (float*)d_out;

    k_stft<<<dim3(NFRAMES, NB), 256>>>(x);
    k_gate<<<NB, 256>>>(Wg1, bg1, Wg2, bg2, Wg3, bg3);

    const int smem_bytes = SMEM_FLOATS * sizeof(float);
    (void)cudaFuncSetAttribute(k_expert,
                               cudaFuncAttributeMaxDynamicSharedMemorySize,
                               smem_bytes);
    k_expert<<<dim3(NTILES, 3, NB), 256, smem_bytes>>>(
        out, x,
        wa3, ba3, wb3, bb3,
        wa5, ba5, wb5, bb5,
        wa7, ba7, wb7, bb7);
}